// round 17
// baseline (speedup 1.0000x reference)
#include <cuda_runtime.h>
#include <cuda_fp16.h>
#include <math.h>

#define Nn 50000
#define Ee 800000
#define Pp 800000

typedef unsigned long long u64;
typedef unsigned int u32;

// ---------------- scratch (device globals; no allocations allowed) ----------
__device__ __half g_x16 [Nn * 128];
__device__ __half g_xw16[Nn * 128];
__device__ float g_as [Nn * 4];
__device__ float g_ad [Nn * 4];
__device__ __half g_h16 [Nn * 128];
__device__ __half g_xw216[Nn * 128];
__device__ float g_as2[Nn];
__device__ float g_ad2[Nn];
__device__ __half g_z16 [Nn * 128];
__device__ __half g_u16 [Nn * 128];
__device__ __half g_v16 [Nn * 128];
__device__ __half g_wt[4 * 128 * 128];   // w1t, w2t, mu_t, mv_t  ([n][k] fp16)
// CSR scratch
__device__ int g_deg[Nn];
__device__ int g_off[Nn + 1];
__device__ int g_cur[Nn];
__device__ int g_blk[64];
__device__ int g_src[Ee];

// ---------------- helpers ----------------------------------------------------
__device__ __forceinline__ float lrelu(float x) { return x > 0.f ? x : 0.2f * x; }
__device__ __forceinline__ float elu1(float x)  { return x > 0.f ? x : __expf(x) - 1.f; }
__device__ __forceinline__ u32 h2u(__half2 h) { return *(u32*)&h; }

// ---------------- conversions ------------------------------------------------
__global__ void k_x16(const float* __restrict__ x) {
    int i = blockIdx.x * 256 + threadIdx.x;
    if (i >= Nn * 32) return;
    float4 v = ((const float4*)x)[i];
    uint2 o;
    o.x = h2u(__floats2half2_rn(v.x, v.y));
    o.y = h2u(__floats2half2_rn(v.z, v.w));
    ((uint2*)g_x16)[i] = o;
}

__global__ void k_wt(const float* __restrict__ W1, const float* __restrict__ W2,
                     const float* __restrict__ mw1) {
    int i = blockIdx.x * 256 + threadIdx.x;
    if (i >= 4 * 16384) return;
    int m = i >> 14, r = i & 16383;
    int n = r >> 7, k = r & 127;
    float v;
    if (m == 0)      v = W1[k * 128 + n];
    else if (m == 1) v = W2[k * 128 + n];
    else if (m == 2) v = mw1[k * 128 + n];
    else             v = mw1[(128 + k) * 128 + n];
    g_wt[i] = __float2half_rn(v);
}

// ---------------- CSR build --------------------------------------------------
__global__ void k_zero() {
    int i = blockIdx.x * blockDim.x + threadIdx.x;
    if (i < Nn) g_deg[i] = 0;
}

__global__ void k_count(const int* __restrict__ ei) {
    int e = blockIdx.x * blockDim.x + threadIdx.x;
    if (e < Ee) atomicAdd(&g_deg[ei[Ee + e]], 1);
}

__global__ void __launch_bounds__(1024) k_scan1() {
    __shared__ int wsum[32];
    int tid = threadIdx.x, lane = tid & 31, w = tid >> 5;
    int i = blockIdx.x * 1024 + tid;
    int v = (i < Nn) ? g_deg[i] : 0;
    int x = v;
#pragma unroll
    for (int off = 1; off < 32; off <<= 1) {
        int t = __shfl_up_sync(0xffffffffu, x, off);
        if (lane >= off) x += t;
    }
    if (lane == 31) wsum[w] = x;
    __syncthreads();
    if (w == 0) {
        int s = wsum[lane];
        int y = s;
#pragma unroll
        for (int off = 1; off < 32; off <<= 1) {
            int t = __shfl_up_sync(0xffffffffu, y, off);
            if (lane >= off) y += t;
        }
        wsum[lane] = y - s;
    }
    __syncthreads();
    int excl = (x - v) + wsum[w];
    if (i < Nn) g_off[i] = excl;
    if (tid == 1023) g_blk[blockIdx.x] = excl + v;
}

__global__ void k_scan2(int nblk) {
    int lane = threadIdx.x;
    int carry = 0;
    for (int c = 0; c < 2; c++) {
        int i = c * 32 + lane;
        int v = (i < nblk) ? g_blk[i] : 0;
        int x = v;
#pragma unroll
        for (int off = 1; off < 32; off <<= 1) {
            int t = __shfl_up_sync(0xffffffffu, x, off);
            if (lane >= off) x += t;
        }
        if (i < nblk) g_blk[i] = carry + x - v;
        carry += __shfl_sync(0xffffffffu, x, 31);
    }
    if (lane == 0) g_off[Nn] = Ee;
}

__global__ void k_scan3() {
    int i = blockIdx.x * blockDim.x + threadIdx.x;
    if (i >= Nn) return;
    int o = g_off[i] + g_blk[i >> 10];
    g_off[i] = o;
    g_cur[i] = o;
}

__global__ void k_fill(const int* __restrict__ ei) {
    int e = blockIdx.x * blockDim.x + threadIdx.x;
    if (e >= Ee) return;
    int s = ei[e], d = ei[Ee + e];
    int pos = atomicAdd(&g_cur[d], 1);
    g_src[pos] = s;
}

// ---------------- fp16 tensor-core GEMM: Ch[M,128] = A16[M,128] @ Bt^T -------
// Bt is [n][k] fp16 (pre-transposed). fp32 accum, fp16 output.
#define HG_SMEM (64 * 136 * 2 + 128 * 136 * 2)

__global__ void __launch_bounds__(256) k_hgemm(const __half* __restrict__ A16,
                                               const __half* __restrict__ Bt,
                                               const float* __restrict__ bias,
                                               __half* __restrict__ Ch, int M) {
    extern __shared__ __half sm[];
    __half* As = sm;               // [64][136]
    __half* Bs = sm + 64 * 136;    // [128][136]
    int tid = threadIdx.x;
    int m0 = blockIdx.x * 64;

#pragma unroll
    for (int r = 0; r < 4; r++) {          // A: 1024 uint4
        int idx = tid + r * 256;
        int row = idx >> 4, c8 = idx & 15;
        uint4 v = make_uint4(0u, 0u, 0u, 0u);
        if (m0 + row < M)
            v = *(const uint4*)(A16 + (size_t)(m0 + row) * 128 + c8 * 8);
        *(uint4*)(As + row * 136 + c8 * 8) = v;
    }
#pragma unroll
    for (int r = 0; r < 8; r++) {          // B: 2048 uint4
        int idx = tid + r * 256;
        int row = idx >> 4, c8 = idx & 15;
        *(uint4*)(Bs + row * 136 + c8 * 8) =
            *(const uint4*)(Bt + (size_t)row * 128 + c8 * 8);
    }
    __syncthreads();

    int warp = tid >> 5, l = tid & 31;
    int n0 = warp * 16;
    int grp = l >> 2, qp = (l & 3) * 2;

    float acc[4][2][4];
#pragma unroll
    for (int mt = 0; mt < 4; mt++)
#pragma unroll
        for (int nt = 0; nt < 2; nt++)
#pragma unroll
            for (int c = 0; c < 4; c++) acc[mt][nt][c] = 0.f;

#pragma unroll
    for (int ks = 0; ks < 8; ks++) {
        int kk = ks * 16 + qp;
        const __half* bp0 = Bs + (n0 + grp) * 136;
        const __half* bp1 = Bs + (n0 + 8 + grp) * 136;
        u32 b00 = *(const u32*)(bp0 + kk);
        u32 b01 = *(const u32*)(bp0 + kk + 8);
        u32 b10 = *(const u32*)(bp1 + kk);
        u32 b11 = *(const u32*)(bp1 + kk + 8);
#pragma unroll
        for (int mt = 0; mt < 4; mt++) {
            const __half* r0 = As + (mt * 16 + grp) * 136;
            const __half* r1 = As + (mt * 16 + 8 + grp) * 136;
            u32 a0 = *(const u32*)(r0 + kk);
            u32 a1 = *(const u32*)(r1 + kk);
            u32 a2 = *(const u32*)(r0 + kk + 8);
            u32 a3 = *(const u32*)(r1 + kk + 8);
            asm volatile(
                "mma.sync.aligned.m16n8k16.row.col.f32.f16.f16.f32 "
                "{%0,%1,%2,%3}, {%4,%5,%6,%7}, {%8,%9}, {%0,%1,%2,%3};"
                : "+f"(acc[mt][0][0]), "+f"(acc[mt][0][1]),
                  "+f"(acc[mt][0][2]), "+f"(acc[mt][0][3])
                : "r"(a0), "r"(a1), "r"(a2), "r"(a3), "r"(b00), "r"(b01));
            asm volatile(
                "mma.sync.aligned.m16n8k16.row.col.f32.f16.f16.f32 "
                "{%0,%1,%2,%3}, {%4,%5,%6,%7}, {%8,%9}, {%0,%1,%2,%3};"
                : "+f"(acc[mt][1][0]), "+f"(acc[mt][1][1]),
                  "+f"(acc[mt][1][2]), "+f"(acc[mt][1][3])
                : "r"(a0), "r"(a1), "r"(a2), "r"(a3), "r"(b10), "r"(b11));
        }
    }

    float bv[2][2] = {{0.f, 0.f}, {0.f, 0.f}};
    if (bias) {
        bv[0][0] = bias[n0 + qp];     bv[0][1] = bias[n0 + qp + 1];
        bv[1][0] = bias[n0 + 8 + qp]; bv[1][1] = bias[n0 + 8 + qp + 1];
    }
#pragma unroll
    for (int mt = 0; mt < 4; mt++) {
        int row0 = m0 + mt * 16 + grp;
        int row1 = row0 + 8;
#pragma unroll
        for (int nt = 0; nt < 2; nt++) {
            int cn = n0 + nt * 8 + qp;
            float c0 = acc[mt][nt][0] + bv[nt][0];
            float c1 = acc[mt][nt][1] + bv[nt][1];
            float c2 = acc[mt][nt][2] + bv[nt][0];
            float c3 = acc[mt][nt][3] + bv[nt][1];
            if (row0 < M)
                *(u32*)(Ch + (size_t)row0 * 128 + cn) =
                    h2u(__floats2half2_rn(c0, c1));
            if (row1 < M)
                *(u32*)(Ch + (size_t)row1 * 128 + cn) =
                    h2u(__floats2half2_rn(c2, c3));
        }
    }
}

// ---------------- attention coefficient dots (fp16 tables) -------------------
__global__ void k_alpha4(const float* __restrict__ aS, const float* __restrict__ aD) {
    int t = blockIdx.x * blockDim.x + threadIdx.x;
    int i = t >> 5, lane = t & 31;
    if (i >= Nn) return;
    uint2 xv = ((const uint2*)g_xw16)[(size_t)i * 32 + lane];
    float2 x0 = __half22float2(*(__half2*)&xv.x);
    float2 x1 = __half22float2(*(__half2*)&xv.y);
    float4 sv = *(const float4*)(aS + lane * 4);
    float4 dv = *(const float4*)(aD + lane * 4);
    float ps = x0.x * sv.x + x0.y * sv.y + x1.x * sv.z + x1.y * sv.w;
    float pd = x0.x * dv.x + x0.y * dv.y + x1.x * dv.z + x1.y * dv.w;
#pragma unroll
    for (int off = 4; off; off >>= 1) {
        ps += __shfl_down_sync(0xffffffffu, ps, off, 8);
        pd += __shfl_down_sync(0xffffffffu, pd, off, 8);
    }
    if ((lane & 7) == 0) {
        int h = lane >> 3;
        g_as[i * 4 + h] = ps;
        g_ad[i * 4 + h] = pd;
    }
}

__global__ void k_alpha1(const float* __restrict__ aS, const float* __restrict__ aD) {
    int t = blockIdx.x * blockDim.x + threadIdx.x;
    int i = t >> 5, lane = t & 31;
    if (i >= Nn) return;
    uint2 xv = ((const uint2*)g_xw216)[(size_t)i * 32 + lane];
    float2 x0 = __half22float2(*(__half2*)&xv.x);
    float2 x1 = __half22float2(*(__half2*)&xv.y);
    float4 sv = *(const float4*)(aS + lane * 4);
    float4 dv = *(const float4*)(aD + lane * 4);
    float ps = x0.x * sv.x + x0.y * sv.y + x1.x * sv.z + x1.y * sv.w;
    float pd = x0.x * dv.x + x0.y * dv.y + x1.x * dv.z + x1.y * dv.w;
#pragma unroll
    for (int off = 16; off; off >>= 1) {
        ps += __shfl_down_sync(0xffffffffu, ps, off);
        pd += __shfl_down_sync(0xffffffffu, pd, off);
    }
    if (lane == 0) { g_as2[i] = ps; g_ad2[i] = pd; }
}

// ---------------- gather-based softmax aggregation (CSR, fp16 gather) --------
__global__ void k_agg1(const float* __restrict__ b1) {
    int t = blockIdx.x * blockDim.x + threadIdx.x;
    int node = t >> 5, lane = t & 31;
    if (node >= Nn) return;
    int h = lane >> 3;
    const uint2* xw = (const uint2*)g_xw16;
    float adh = g_ad[node * 4 + h];
    float ex = __expf(lrelu(g_as[node * 4 + h] + adh));
    uint2 sv = xw[(size_t)node * 32 + lane];
    float2 s0f = __half22float2(*(__half2*)&sv.x);
    float2 s1f = __half22float2(*(__half2*)&sv.y);
    float4 acc;
    acc.x = ex * s0f.x; acc.y = ex * s0f.y;
    acc.z = ex * s1f.x; acc.w = ex * s1f.y;
    float den = ex;
    int e = g_off[node], e1 = g_off[node + 1];
    for (; e + 2 <= e1; e += 2) {
        int n0 = g_src[e], n1 = g_src[e + 1];
        float l0 = g_as[n0 * 4 + h], l1 = g_as[n1 * 4 + h];
        uint2 w0 = xw[(size_t)n0 * 32 + lane];
        uint2 w1 = xw[(size_t)n1 * 32 + lane];
        float x0 = __expf(lrelu(l0 + adh)), x1 = __expf(lrelu(l1 + adh));
        float2 a0 = __half22float2(*(__half2*)&w0.x);
        float2 a1 = __half22float2(*(__half2*)&w0.y);
        float2 b0 = __half22float2(*(__half2*)&w1.x);
        float2 b1 = __half22float2(*(__half2*)&w1.y);
        acc.x += x0 * a0.x + x1 * b0.x; acc.y += x0 * a0.y + x1 * b0.y;
        acc.z += x0 * a1.x + x1 * b1.x; acc.w += x0 * a1.y + x1 * b1.y;
        den += x0 + x1;
    }
    if (e < e1) {
        int n0 = g_src[e];
        float x0 = __expf(lrelu(g_as[n0 * 4 + h] + adh));
        uint2 w0 = xw[(size_t)n0 * 32 + lane];
        float2 a0 = __half22float2(*(__half2*)&w0.x);
        float2 a1 = __half22float2(*(__half2*)&w0.y);
        acc.x += x0 * a0.x; acc.y += x0 * a0.y;
        acc.z += x0 * a1.x; acc.w += x0 * a1.y;
        den += x0;
    }
    float inv = 1.f / den;
    float4 b = ((const float4*)b1)[lane];
    uint2 o;
    o.x = h2u(__floats2half2_rn(elu1(acc.x * inv + b.x), elu1(acc.y * inv + b.y)));
    o.y = h2u(__floats2half2_rn(elu1(acc.z * inv + b.z), elu1(acc.w * inv + b.w)));
    ((uint2*)g_h16)[(size_t)node * 32 + lane] = o;
}

__global__ void k_agg2(const float* __restrict__ b2) {
    int t = blockIdx.x * blockDim.x + threadIdx.x;
    int node = t >> 5, lane = t & 31;
    if (node >= Nn) return;
    const uint2* xw = (const uint2*)g_xw216;
    float adh = g_ad2[node];
    float ex = __expf(lrelu(g_as2[node] + adh));
    uint2 sv = xw[(size_t)node * 32 + lane];
    float2 s0f = __half22float2(*(__half2*)&sv.x);
    float2 s1f = __half22float2(*(__half2*)&sv.y);
    float4 acc;
    acc.x = ex * s0f.x; acc.y = ex * s0f.y;
    acc.z = ex * s1f.x; acc.w = ex * s1f.y;
    float den = ex;
    int e = g_off[node], e1 = g_off[node + 1];
    for (; e + 2 <= e1; e += 2) {
        int n0 = g_src[e], n1 = g_src[e + 1];
        float l0 = g_as2[n0], l1 = g_as2[n1];
        uint2 w0 = xw[(size_t)n0 * 32 + lane];
        uint2 w1 = xw[(size_t)n1 * 32 + lane];
        float x0 = __expf(lrelu(l0 + adh)), x1 = __expf(lrelu(l1 + adh));
        float2 a0 = __half22float2(*(__half2*)&w0.x);
        float2 a1 = __half22float2(*(__half2*)&w0.y);
        float2 b0 = __half22float2(*(__half2*)&w1.x);
        float2 b1 = __half22float2(*(__half2*)&w1.y);
        acc.x += x0 * a0.x + x1 * b0.x; acc.y += x0 * a0.y + x1 * b0.y;
        acc.z += x0 * a1.x + x1 * b1.x; acc.w += x0 * a1.y + x1 * b1.y;
        den += x0 + x1;
    }
    if (e < e1) {
        int n0 = g_src[e];
        float x0 = __expf(lrelu(g_as2[n0] + adh));
        uint2 w0 = xw[(size_t)n0 * 32 + lane];
        float2 a0 = __half22float2(*(__half2*)&w0.x);
        float2 a1 = __half22float2(*(__half2*)&w0.y);
        acc.x += x0 * a0.x; acc.y += x0 * a0.y;
        acc.z += x0 * a1.x; acc.w += x0 * a1.y;
        den += x0;
    }
    float inv = 1.f / den;
    float4 b = ((const float4*)b2)[lane];
    uint2 o;
    o.x = h2u(__floats2half2_rn(acc.x * inv + b.x, acc.y * inv + b.y));
    o.y = h2u(__floats2half2_rn(acc.z * inv + b.z, acc.w * inv + b.w));
    ((uint2*)g_z16)[(size_t)node * 32 + lane] = o;
}

// ---------------- edge-pair MLP: fp16 tensor-core GEMM (unchanged) -----------
#define MTC 128
#define TROW 136
#define NT_TC (Pp / MTC)
#define MLPB 444

__global__ void __launch_bounds__(256, 3) k_mlp(const int* __restrict__ ep,
                                                const float* __restrict__ mw2,
                                                const float* __restrict__ mb2,
                                                const float* __restrict__ mw3,
                                                const float* __restrict__ mb3,
                                                float* __restrict__ out) {
    __shared__ __align__(16) __half T[MTC * TROW];
    __shared__ float part[8][128];

    int tid = threadIdx.x;
    int warp = tid >> 5, l = tid & 31;
    int n0 = warp * 8;
    int grp = l >> 2;
    int qp  = (l & 3) * 2;

    u32 bf[8][2];
    {
        int bn = n0 + grp;
#pragma unroll
        for (int ks = 0; ks < 8; ks++) {
            int k0 = ks * 16 + qp;
            bf[ks][0] = h2u(__floats2half2_rn(mw2[(k0 + 0) * 64 + bn],
                                              mw2[(k0 + 1) * 64 + bn]));
            bf[ks][1] = h2u(__floats2half2_rn(mw2[(k0 + 8) * 64 + bn],
                                              mw2[(k0 + 9) * 64 + bn]));
        }
    }
    int ccol = n0 + qp;
    float cb0 = __ldg(mb2 + ccol), cb1 = __ldg(mb2 + ccol + 1);
    float w30 = __ldg(mw3 + ccol), w31 = __ldg(mw3 + ccol + 1);
    float mb3v = __ldg(mb3);

    int p = tid >> 1, phalf = tid & 1;
    const __half2 hz = __float2half2_rn(0.f);

    for (int tile = blockIdx.x; tile < NT_TC; tile += gridDim.x) {
        int P0 = tile * MTC;
        __syncthreads();
        {
            int i = ep[P0 + p], j = ep[Pp + P0 + p];
            const uint4* ur = (const uint4*)g_u16 + (size_t)i * 16 + phalf * 8;
            const uint4* vr = (const uint4*)g_v16 + (size_t)j * 16 + phalf * 8;
            uint4* dst = (uint4*)((char*)T + p * (TROW * 2) + phalf * 128);
#pragma unroll
            for (int r = 0; r < 8; r++) {
                uint4 a = ur[r], b = vr[r], o;
                o.x = h2u(__hmax2(__hadd2(*(__half2*)&a.x, *(__half2*)&b.x), hz));
                o.y = h2u(__hmax2(__hadd2(*(__half2*)&a.y, *(__half2*)&b.y), hz));
                o.z = h2u(__hmax2(__hadd2(*(__half2*)&a.z, *(__half2*)&b.z), hz));
                o.w = h2u(__hmax2(__hadd2(*(__half2*)&a.w, *(__half2*)&b.w), hz));
                dst[r] = o;
            }
        }
        __syncthreads();

#pragma unroll 2
        for (int slab = 0; slab < 8; slab++) {
            int m0 = slab * 16;
            float c0 = cb0, c1 = cb1, c2 = cb0, c3 = cb1;
            const __half* r0 = T + (m0 + grp) * TROW;
            const __half* r1 = T + (m0 + grp + 8) * TROW;
#pragma unroll
            for (int ks = 0; ks < 8; ks++) {
                int kk = ks * 16 + qp;
                u32 a0 = *(const u32*)(r0 + kk);
                u32 a1 = *(const u32*)(r1 + kk);
                u32 a2 = *(const u32*)(r0 + kk + 8);
                u32 a3 = *(const u32*)(r1 + kk + 8);
                asm volatile(
                    "mma.sync.aligned.m16n8k16.row.col.f32.f16.f16.f32 "
                    "{%0,%1,%2,%3}, {%4,%5,%6,%7}, {%8,%9}, {%0,%1,%2,%3};"
                    : "+f"(c0), "+f"(c1), "+f"(c2), "+f"(c3)
                    : "r"(a0), "r"(a1), "r"(a2), "r"(a3),
                      "r"(bf[ks][0]), "r"(bf[ks][1]));
            }
            float pv0 = fmaxf(c0, 0.f) * w30 + fmaxf(c1, 0.f) * w31;
            float pv1 = fmaxf(c2, 0.f) * w30 + fmaxf(c3, 0.f) * w31;
            pv0 += __shfl_xor_sync(0xffffffffu, pv0, 1);
            pv0 += __shfl_xor_sync(0xffffffffu, pv0, 2);
            pv1 += __shfl_xor_sync(0xffffffffu, pv1, 1);
            pv1 += __shfl_xor_sync(0xffffffffu, pv1, 2);
            if ((l & 3) == 0) {
                part[warp][m0 + grp]     = pv0;
                part[warp][m0 + grp + 8] = pv1;
            }
        }
        __syncthreads();

        if (tid < 128) {
            float s = mb3v;
#pragma unroll
            for (int w = 0; w < 8; w++) s += part[w][tid];
            out[P0 + tid] = 1.f / (1.f + __expf(-s));
        }
    }
}

// ---------------- launch ------------------------------------------------------
extern "C" void kernel_launch(void* const* d_in, const int* in_sizes, int n_in,
                              void* d_out, int out_size) {
    const float* x   = (const float*)d_in[0];
    const int*   ei  = (const int*)  d_in[1];
    const int*   ep  = (const int*)  d_in[2];
    const float* W1  = (const float*)d_in[3];
    const float* as1 = (const float*)d_in[4];
    const float* ad1 = (const float*)d_in[5];
    const float* b1  = (const float*)d_in[6];
    const float* W2  = (const float*)d_in[7];
    const float* as2 = (const float*)d_in[8];
    const float* ad2 = (const float*)d_in[9];
    const float* b2  = (const float*)d_in[10];
    const float* mw1 = (const float*)d_in[11];
    const float* mb1 = (const float*)d_in[12];
    const float* mw2 = (const float*)d_in[13];
    const float* mb2 = (const float*)d_in[14];
    const float* mw3 = (const float*)d_in[15];
    const float* mb3 = (const float*)d_in[16];
    float* out = (float*)d_out;

    __half *p_x16, *p_xw16, *p_h16, *p_xw216, *p_z16, *p_u16, *p_v16, *p_wt;
    cudaGetSymbolAddress((void**)&p_x16,   g_x16);
    cudaGetSymbolAddress((void**)&p_xw16,  g_xw16);
    cudaGetSymbolAddress((void**)&p_h16,   g_h16);
    cudaGetSymbolAddress((void**)&p_xw216, g_xw216);
    cudaGetSymbolAddress((void**)&p_z16,   g_z16);
    cudaGetSymbolAddress((void**)&p_u16,   g_u16);
    cudaGetSymbolAddress((void**)&p_v16,   g_v16);
    cudaGetSymbolAddress((void**)&p_wt,    g_wt);

    cudaFuncSetAttribute(k_hgemm,
                         cudaFuncAttributeMaxDynamicSharedMemorySize, HG_SMEM);

    const int eb  = (Ee + 255) / 256;
    const int nb  = (Nn + 255) / 256;
    const int gb  = (Nn + 63) / 64;
    const int ab  = (Nn + 7) / 8;
    const int sb  = (Nn + 1023) / 1024;

    // Conversions + CSR build + layer-1 GEMM (agg1 near the ncu window)
    k_x16<<<(Nn * 32 + 255) / 256, 256>>>(x);
    k_wt<<<(4 * 16384 + 255) / 256, 256>>>(W1, W2, mw1);
    k_zero<<<nb, 256>>>();
    k_hgemm<<<gb, 256, HG_SMEM>>>(p_x16, p_wt, nullptr, p_xw16, Nn);
    k_count<<<eb, 256>>>(ei);
    k_scan1<<<sb, 1024>>>();
    k_scan2<<<1, 32>>>(sb);
    k_scan3<<<nb, 256>>>();
    k_fill<<<eb, 256>>>(ei);

    // Layer 1 GAT
    k_alpha4<<<ab, 256>>>(as1, ad1);
    k_agg1<<<ab, 256>>>(b1);

    // Layer 2 GAT
    k_hgemm<<<gb, 256, HG_SMEM>>>(p_h16, p_wt + 16384, nullptr, p_xw216, Nn);
    k_alpha1<<<ab, 256>>>(as2, ad2);
    k_agg2<<<ab, 256>>>(b2);

    // Pair MLP precompute: u = z@mw1[:128]+mb1 ; v = z@mw1[128:]
    k_hgemm<<<gb, 256, HG_SMEM>>>(p_z16, p_wt + 2 * 16384, mb1, p_u16, Nn);
    k_hgemm<<<gb, 256, HG_SMEM>>>(p_z16, p_wt + 3 * 16384, nullptr, p_v16, Nn);

    // Edge-pair MLP (persistent tensor-core GEMM)
    k_mlp<<<MLPB, 256>>>(ep, mw2, mb2, mw3, mb3, out);
}